// round 4
// baseline (speedup 1.0000x reference)
#include <cuda_runtime.h>
#include <stdint.h>
#include <math.h>

#define BATCH   2
#define SEQ     2048
#define DMODEL  1024
#define NHEAD   16
#define DK      64
#define MTOT    (BATCH*SEQ)
#define OUT_OFF ((size_t)MTOT*DMODEL)

// Scratch: projected Q/K/V and attention output (pre-W_o)
__device__ float g_qp[MTOT*DMODEL];
__device__ float g_kp[MTOT*DMODEL];
__device__ float g_vp[MTOT*DMODEL];
__device__ float g_ao[MTOT*DMODEL];

// ---------------------------------------------------------------------------
__device__ __forceinline__ uint32_t f2tf32(float x) {
    uint32_t u;
    asm("cvt.rna.tf32.f32 %0, %1;" : "=r"(u) : "f"(x));
    return u;
}

__device__ __forceinline__ float4 cvt4(float4 v) {
    float4 r;
    r.x = __uint_as_float(f2tf32(v.x));
    r.y = __uint_as_float(f2tf32(v.y));
    r.z = __uint_as_float(f2tf32(v.z));
    r.w = __uint_as_float(f2tf32(v.w));
    return r;
}

__device__ __forceinline__ void mma_tf32(float* d, const uint32_t* a, const uint32_t* b) {
    asm volatile(
        "mma.sync.aligned.m16n8k8.row.col.f32.tf32.tf32.f32 "
        "{%0,%1,%2,%3}, {%4,%5,%6,%7}, {%8,%9}, {%0,%1,%2,%3};"
        : "+f"(d[0]), "+f"(d[1]), "+f"(d[2]), "+f"(d[3])
        : "r"(a[0]), "r"(a[1]), "r"(a[2]), "r"(a[3]), "r"(b[0]), "r"(b[1]));
}

// Fast exp on the FMA pipe (magic rounding + deg-6 poly), rel err ~1e-7.
__device__ __forceinline__ float fast_exp(float x) {
    x = fmaxf(x, -80.f);
    float t = x * 1.4426950408889634f;
    float z = t + 12582912.f;                 // round to nearest int (magic)
    int   i = __float_as_int(z) - 0x4B400000;
    float f = t - (z - 12582912.f);
    float y = f * 0.6931471805599453f;
    float p = 1.f + y*(1.f + y*(0.5f + y*(0.16666667f + y*(0.041666668f +
              y*(0.008333334f + y*0.0013888889f)))));
    return p * __int_as_float((i + 127) << 23);
}

// ---------------------------------------------------------------------------
// NT: C[M,N] = alpha * A[M,K] @ B[N,K]^T. BM=BN=128, BK=16. (projections)
// ---------------------------------------------------------------------------
__global__ __launch_bounds__(256, 2) void gemm_tf32_nt(
    const float* __restrict__ A, const float* __restrict__ B, float* __restrict__ C,
    int K, int lda, int ldb, int ldc, float alpha)
{
    __shared__ float As[2][128][20];
    __shared__ float Bs[2][128][20];

    const int tid  = threadIdx.x;
    const int lane = tid & 31;
    const int warp = tid >> 5;
    const int wm   = warp >> 2;
    const int wn   = warp & 3;
    const int q    = lane & 3;
    const int lr   = lane >> 2;

    const int mBase = blockIdx.y * 128;
    const int nBase = blockIdx.x * 128;

    const int r0 = tid >> 2;
    const int c4 = (tid & 3) << 2;

    float acc[4][4][4];
    #pragma unroll
    for (int i = 0; i < 4; i++)
        #pragma unroll
        for (int j = 0; j < 4; j++)
            #pragma unroll
            for (int t = 0; t < 4; t++) acc[i][j][t] = 0.f;

    const float* Ag = A + (size_t)mBase * lda;
    const float* Bg = B + (size_t)nBase * ldb;

    float4 pa0 = *(const float4*)(Ag + (size_t)r0 * lda + c4);
    float4 pa1 = *(const float4*)(Ag + (size_t)(r0 + 64) * lda + c4);
    float4 pb0 = *(const float4*)(Bg + (size_t)r0 * ldb + c4);
    float4 pb1 = *(const float4*)(Bg + (size_t)(r0 + 64) * ldb + c4);
    *(float4*)&As[0][r0][c4]      = cvt4(pa0);
    *(float4*)&As[0][r0 + 64][c4] = cvt4(pa1);
    *(float4*)&Bs[0][r0][c4]      = cvt4(pb0);
    *(float4*)&Bs[0][r0 + 64][c4] = cvt4(pb1);
    __syncthreads();

    const int nc = K >> 4;
    for (int ch = 0; ch < nc; ch++) {
        const int cur  = ch & 1;
        const bool more = (ch + 1 < nc);
        if (more) {
            const int k0 = (ch + 1) << 4;
            pa0 = *(const float4*)(Ag + (size_t)r0 * lda + k0 + c4);
            pa1 = *(const float4*)(Ag + (size_t)(r0 + 64) * lda + k0 + c4);
            pb0 = *(const float4*)(Bg + (size_t)r0 * ldb + k0 + c4);
            pb1 = *(const float4*)(Bg + (size_t)(r0 + 64) * ldb + k0 + c4);
        }

        #pragma unroll
        for (int ks = 0; ks < 2; ks++) {
            const int kb = ks * 8 + q;
            uint32_t af[4][4], bf[4][2];
            #pragma unroll
            for (int mi = 0; mi < 4; mi++) {
                const int m0 = wm * 64 + mi * 16 + lr;
                af[mi][0] = __float_as_uint(As[cur][m0][kb]);
                af[mi][1] = __float_as_uint(As[cur][m0 + 8][kb]);
                af[mi][2] = __float_as_uint(As[cur][m0][kb + 4]);
                af[mi][3] = __float_as_uint(As[cur][m0 + 8][kb + 4]);
            }
            #pragma unroll
            for (int ni = 0; ni < 4; ni++) {
                const int n0 = wn * 32 + ni * 8 + lr;
                bf[ni][0] = __float_as_uint(Bs[cur][n0][kb]);
                bf[ni][1] = __float_as_uint(Bs[cur][n0][kb + 4]);
            }
            #pragma unroll
            for (int mi = 0; mi < 4; mi++)
                #pragma unroll
                for (int ni = 0; ni < 4; ni++)
                    mma_tf32(acc[mi][ni], af[mi], bf[ni]);
        }
        __syncthreads();
        if (more) {
            const int nxt = cur ^ 1;
            *(float4*)&As[nxt][r0][c4]      = cvt4(pa0);
            *(float4*)&As[nxt][r0 + 64][c4] = cvt4(pa1);
            *(float4*)&Bs[nxt][r0][c4]      = cvt4(pb0);
            *(float4*)&Bs[nxt][r0 + 64][c4] = cvt4(pb1);
            __syncthreads();
        }
    }

    #pragma unroll
    for (int mi = 0; mi < 4; mi++) {
        const int row0 = mBase + wm * 64 + mi * 16 + lr;
        #pragma unroll
        for (int ni = 0; ni < 4; ni++) {
            const int col = nBase + wn * 32 + ni * 8 + q * 2;
            *(float2*)&C[(size_t)row0 * ldc + col] =
                make_float2(acc[mi][ni][0] * alpha, acc[mi][ni][1] * alpha);
            *(float2*)&C[(size_t)(row0 + 8) * ldc + col] =
                make_float2(acc[mi][ni][2] * alpha, acc[mi][ni][3] * alpha);
        }
    }
}

// ---------------------------------------------------------------------------
// Fused scores + softmax: per (bh, 128-row block), two passes over N=2048.
// Q frags register-resident; K tiles streamed through smem (L2-resident).
// Pass 1: online (max, sum) per row. Pass 2: recompute, write normalized P
// once (coalesced via smem staging).
// 8 warps, warp w owns rows w*16 .. w*16+15 (full 128-col width).
// ---------------------------------------------------------------------------
__global__ __launch_bounds__(256) void scores_softmax_kernel(
    const float* __restrict__ qp, const float* __restrict__ kp, float* __restrict__ wts)
{
    const int bh = blockIdx.y;
    const int b  = bh >> 4, h = bh & 15;
    const int rowBase = blockIdx.x * 128;

    const float* Qg = qp + (size_t)b * SEQ * DMODEL + h * DK + (size_t)rowBase * DMODEL;
    const float* Kg = kp + (size_t)b * SEQ * DMODEL + h * DK;
    float*       P  = wts + (size_t)bh * SEQ * SEQ + (size_t)rowBase * SEQ;

    __shared__ float sk[128][68];            // K tile / Q staging / P staging
    float* stg = &sk[0][0];                  // 64x132 staging view (8448 <= 8704)

    const int tid  = threadIdx.x;
    const int lane = tid & 31;
    const int warp = tid >> 5;
    const int q    = lane & 3;
    const int lr   = lane >> 2;

    // ---- stage Q (scaled by 1/8, exact) and extract A fragments ----
    #pragma unroll
    for (int it = 0; it < 2; it++) {
        int idx = tid + 256 * it;            // 0..511 covers 128x64/16
        int row = idx >> 2;
        int c4  = (idx & 3) << 4;            // 0,16,32,48
        #pragma unroll
        for (int j = 0; j < 4; j++) {
            float4 v = *(const float4*)(Qg + (size_t)row * DMODEL + c4 + j * 4);
            v.x *= 0.125f; v.y *= 0.125f; v.z *= 0.125f; v.w *= 0.125f;
            *(float4*)&sk[row][c4 + j * 4] = cvt4(v);
        }
    }
    __syncthreads();

    uint32_t af[8][4];
    {
        const int m0 = warp * 16 + lr;
        #pragma unroll
        for (int ks = 0; ks < 8; ks++) {
            const int kb = ks * 8 + q;
            af[ks][0] = __float_as_uint(sk[m0][kb]);
            af[ks][1] = __float_as_uint(sk[m0 + 8][kb]);
            af[ks][2] = __float_as_uint(sk[m0][kb + 4]);
            af[ks][3] = __float_as_uint(sk[m0 + 8][kb + 4]);
        }
    }

    float m0r = -1e30f, s0r = 0.f;           // row warp*16+lr
    float m1r = -1e30f, s1r = 0.f;           // row warp*16+lr+8

    float acc[16][4];

    // ================= PASS 1: online max/sum =================
    for (int t = 0; t < 16; t++) {
        __syncthreads();
        const int n0 = t * 128;
        #pragma unroll
        for (int it = 0; it < 8; it++) {
            int idx = tid + 256 * it;
            int row = idx >> 4;
            int c4  = (idx & 15) << 2;
            float4 v = *(const float4*)(Kg + (size_t)(n0 + row) * DMODEL + c4);
            *(float4*)&sk[row][c4] = cvt4(v);
        }
        __syncthreads();

        #pragma unroll
        for (int ni = 0; ni < 16; ni++) {
            acc[ni][0] = acc[ni][1] = acc[ni][2] = acc[ni][3] = 0.f;
            const int n0r = ni * 8 + lr;
            #pragma unroll
            for (int ks = 0; ks < 8; ks++) {
                uint32_t bf[2];
                bf[0] = __float_as_uint(sk[n0r][ks * 8 + q]);
                bf[1] = __float_as_uint(sk[n0r][ks * 8 + q + 4]);
                mma_tf32(acc[ni], af[ks], bf);
            }
        }

        float tm0 = -1e30f, tm1 = -1e30f;
        #pragma unroll
        for (int ni = 0; ni < 16; ni++) {
            tm0 = fmaxf(tm0, fmaxf(acc[ni][0], acc[ni][1]));
            tm1 = fmaxf(tm1, fmaxf(acc[ni][2], acc[ni][3]));
        }
        float mn0 = fmaxf(m0r, tm0);
        float mn1 = fmaxf(m1r, tm1);
        s0r *= fast_exp(m0r - mn0);
        s1r *= fast_exp(m1r - mn1);
        m0r = mn0; m1r = mn1;
        #pragma unroll
        for (int ni = 0; ni < 16; ni++) {
            s0r += fast_exp(acc[ni][0] - m0r) + fast_exp(acc[ni][1] - m0r);
            s1r += fast_exp(acc[ni][2] - m1r) + fast_exp(acc[ni][3] - m1r);
        }
    }

    // combine across the 4 quad lanes sharing each row
    #pragma unroll
    for (int o = 1; o <= 2; o <<= 1) {
        float mo = __shfl_xor_sync(0xFFFFFFFFu, m0r, o);
        float so = __shfl_xor_sync(0xFFFFFFFFu, s0r, o);
        float mn = fmaxf(m0r, mo);
        s0r = s0r * fast_exp(m0r - mn) + so * fast_exp(mo - mn);
        m0r = mn;
        mo = __shfl_xor_sync(0xFFFFFFFFu, m1r, o);
        so = __shfl_xor_sync(0xFFFFFFFFu, s1r, o);
        mn = fmaxf(m1r, mo);
        s1r = s1r * fast_exp(m1r - mn) + so * fast_exp(mo - mn);
        m1r = mn;
    }
    const float inv0 = 1.f / s0r;
    const float inv1 = 1.f / s1r;

    // ================= PASS 2: recompute, normalize, write =================
    const int orow = (tid >> 5) * 8;
    const int ocol = (tid & 31) * 4;
    for (int t = 0; t < 16; t++) {
        __syncthreads();
        const int n0 = t * 128;
        #pragma unroll
        for (int it = 0; it < 8; it++) {
            int idx = tid + 256 * it;
            int row = idx >> 4;
            int c4  = (idx & 15) << 2;
            float4 v = *(const float4*)(Kg + (size_t)(n0 + row) * DMODEL + c4);
            *(float4*)&sk[row][c4] = cvt4(v);
        }
        __syncthreads();

        #pragma unroll
        for (int ni = 0; ni < 16; ni++) {
            acc[ni][0] = acc[ni][1] = acc[ni][2] = acc[ni][3] = 0.f;
            const int n0r = ni * 8 + lr;
            #pragma unroll
            for (int ks = 0; ks < 8; ks++) {
                uint32_t bf[2];
                bf[0] = __float_as_uint(sk[n0r][ks * 8 + q]);
                bf[1] = __float_as_uint(sk[n0r][ks * 8 + q + 4]);
                mma_tf32(acc[ni], af[ks], bf);
            }
        }

        #pragma unroll
        for (int half = 0; half < 2; half++) {
            __syncthreads();                 // smem free (MMA reads / prior copy done)
            if ((warp >> 2) == half) {
                const int rb = (warp & 3) * 16;
                #pragma unroll
                for (int ni = 0; ni < 16; ni++) {
                    float e0 = fast_exp(acc[ni][0] - m0r) * inv0;
                    float e1 = fast_exp(acc[ni][1] - m0r) * inv0;
                    float e2 = fast_exp(acc[ni][2] - m1r) * inv1;
                    float e3 = fast_exp(acc[ni][3] - m1r) * inv1;
                    *(float2*)&stg[(rb + lr) * 132 + ni * 8 + q * 2]     = make_float2(e0, e1);
                    *(float2*)&stg[(rb + lr + 8) * 132 + ni * 8 + q * 2] = make_float2(e2, e3);
                }
            }
            __syncthreads();
            #pragma unroll
            for (int i = 0; i < 8; i++) {
                const int row = orow + i;
                *(float4*)&P[(size_t)(half * 64 + row) * SEQ + n0 + ocol] =
                    *(const float4*)&stg[row * 132 + ocol];
            }
        }
    }
}

// ---------------------------------------------------------------------------
// NN: C[M,64] = A[M,K] @ B[K,64]. Used for P @ V.
// ---------------------------------------------------------------------------
__global__ __launch_bounds__(256, 2) void gemm_tf32_nn64(
    const float* __restrict__ A, const float* __restrict__ B, float* __restrict__ C,
    int K, int lda, int ldb, int ldc)
{
    const int z = blockIdx.z;
    const int b = z >> 4, h = z & 15;
    A += (size_t)z * SEQ * SEQ;
    B += (size_t)b * SEQ * DMODEL + h * DK;
    C += (size_t)b * SEQ * DMODEL + h * DK;

    __shared__ float As[2][128][20];
    __shared__ float Bs[2][16][72];

    const int tid  = threadIdx.x;
    const int lane = tid & 31;
    const int warp = tid >> 5;
    const int wm   = warp >> 1;
    const int wn   = warp & 1;
    const int q    = lane & 3;
    const int lr   = lane >> 2;

    const int mBase = blockIdx.y * 128;

    const int r0 = tid >> 2;
    const int c4 = (tid & 3) << 2;
    const int kr = tid >> 4;
    const int n4 = (tid & 15) << 2;

    float acc[2][4][4];
    #pragma unroll
    for (int i = 0; i < 2; i++)
        #pragma unroll
        for (int j = 0; j < 4; j++)
            #pragma unroll
            for (int t = 0; t < 4; t++) acc[i][j][t] = 0.f;

    const float* Ag = A + (size_t)mBase * lda;

    float4 pa0 = *(const float4*)(Ag + (size_t)r0 * lda + c4);
    float4 pa1 = *(const float4*)(Ag + (size_t)(r0 + 64) * lda + c4);
    float4 pb  = *(const float4*)(B + (size_t)kr * ldb + n4);
    *(float4*)&As[0][r0][c4]      = cvt4(pa0);
    *(float4*)&As[0][r0 + 64][c4] = cvt4(pa1);
    *(float4*)&Bs[0][kr][n4]      = cvt4(pb);
    __syncthreads();

    const int nc = K >> 4;
    for (int ch = 0; ch < nc; ch++) {
        const int cur  = ch & 1;
        const bool more = (ch + 1 < nc);
        if (more) {
            const int k0 = (ch + 1) << 4;
            pa0 = *(const float4*)(Ag + (size_t)r0 * lda + k0 + c4);
            pa1 = *(const float4*)(Ag + (size_t)(r0 + 64) * lda + k0 + c4);
            pb  = *(const float4*)(B + (size_t)(k0 + kr) * ldb + n4);
        }

        #pragma unroll
        for (int ks = 0; ks < 2; ks++) {
            const int kb = ks * 8 + q;
            uint32_t af[2][4], bf[4][2];
            #pragma unroll
            for (int mi = 0; mi < 2; mi++) {
                const int m0 = wm * 32 + mi * 16 + lr;
                af[mi][0] = __float_as_uint(As[cur][m0][kb]);
                af[mi][1] = __float_as_uint(As[cur][m0 + 8][kb]);
                af[mi][2] = __float_as_uint(As[cur][m0][kb + 4]);
                af[mi][3] = __float_as_uint(As[cur][m0 + 8][kb + 4]);
            }
            #pragma unroll
            for (int ni = 0; ni < 4; ni++) {
                const int n0 = wn * 32 + ni * 8 + lr;
                bf[ni][0] = __float_as_uint(Bs[cur][kb][n0]);
                bf[ni][1] = __float_as_uint(Bs[cur][kb + 4][n0]);
            }
            #pragma unroll
            for (int mi = 0; mi < 2; mi++)
                #pragma unroll
                for (int ni = 0; ni < 4; ni++)
                    mma_tf32(acc[mi][ni], af[mi], bf[ni]);
        }
        __syncthreads();
        if (more) {
            const int nxt = cur ^ 1;
            *(float4*)&As[nxt][r0][c4]      = cvt4(pa0);
            *(float4*)&As[nxt][r0 + 64][c4] = cvt4(pa1);
            *(float4*)&Bs[nxt][kr][n4]      = cvt4(pb);
            __syncthreads();
        }
    }

    #pragma unroll
    for (int mi = 0; mi < 2; mi++) {
        const int row0 = mBase + wm * 32 + mi * 16 + lr;
        #pragma unroll
        for (int ni = 0; ni < 4; ni++) {
            const int col = wn * 32 + ni * 8 + q * 2;
            *(float2*)&C[(size_t)row0 * ldc + col] =
                make_float2(acc[mi][ni][0], acc[mi][ni][1]);
            *(float2*)&C[(size_t)(row0 + 8) * ldc + col] =
                make_float2(acc[mi][ni][2], acc[mi][ni][3]);
        }
    }
}

// ---------------------------------------------------------------------------
extern "C" void kernel_launch(void* const* d_in, const int* in_sizes, int n_in,
                              void* d_out, int out_size)
{
    const float* q  = (const float*)d_in[0];
    const float* k  = (const float*)d_in[1];
    const float* v  = (const float*)d_in[2];
    const float* Wq = (const float*)d_in[3];
    const float* Wk = (const float*)d_in[4];
    const float* Wv = (const float*)d_in[5];
    const float* Wo = (const float*)d_in[6];
    float* out = (float*)d_out;
    float* wts = out + OUT_OFF;

    float *qp, *kp, *vp, *ao;
    cudaGetSymbolAddress((void**)&qp, g_qp);
    cudaGetSymbolAddress((void**)&kp, g_kp);
    cudaGetSymbolAddress((void**)&vp, g_vp);
    cudaGetSymbolAddress((void**)&ao, g_ao);

    const dim3 thr(256);

    // Projections: [4096,1024] @ [1024,1024]^T
    gemm_tf32_nt<<<dim3(8, 32), thr>>>(q, Wq, qp, DMODEL, DMODEL, DMODEL, DMODEL, 1.f);
    gemm_tf32_nt<<<dim3(8, 32), thr>>>(k, Wk, kp, DMODEL, DMODEL, DMODEL, DMODEL, 1.f);
    gemm_tf32_nt<<<dim3(8, 32), thr>>>(v, Wv, vp, DMODEL, DMODEL, DMODEL, DMODEL, 1.f);

    // Fused scores + softmax -> normalized P written once
    scores_softmax_kernel<<<dim3(16, 32), thr>>>(qp, kp, wts);

    // P @ V -> attn_out
    gemm_tf32_nn64<<<dim3(1, 16, 32), thr>>>(wts, vp, ao, SEQ, SEQ, DMODEL, DMODEL);

    // Output projection
    gemm_tf32_nt<<<dim3(8, 32), thr>>>(ao, Wo, out, DMODEL, DMODEL, DMODEL, DMODEL, 1.f);
}

// round 5
// speedup vs baseline: 1.2947x; 1.2947x over previous
#include <cuda_runtime.h>
#include <stdint.h>
#include <math.h>

#define BATCH   2
#define SEQ     2048
#define DMODEL  1024
#define NHEAD   16
#define DK      64
#define MTOT    (BATCH*SEQ)
#define OUT_OFF ((size_t)MTOT*DMODEL)

// Scratch: projected Q/K/V and attention output (pre-W_o)
__device__ float g_qp[MTOT*DMODEL];
__device__ float g_kp[MTOT*DMODEL];
__device__ float g_vp[MTOT*DMODEL];
__device__ float g_ao[MTOT*DMODEL];

// ---------------------------------------------------------------------------
__device__ __forceinline__ uint32_t f2tf32(float x) {
    uint32_t u;
    asm("cvt.rna.tf32.f32 %0, %1;" : "=r"(u) : "f"(x));
    return u;
}

__device__ __forceinline__ void mma_tf32(float* d, const uint32_t* a, const uint32_t* b) {
    asm volatile(
        "mma.sync.aligned.m16n8k8.row.col.f32.tf32.tf32.f32 "
        "{%0,%1,%2,%3}, {%4,%5,%6,%7}, {%8,%9}, {%0,%1,%2,%3};"
        : "+f"(d[0]), "+f"(d[1]), "+f"(d[2]), "+f"(d[3])
        : "r"(a[0]), "r"(a[1]), "r"(a[2]), "r"(a[3]), "r"(b[0]), "r"(b[1]));
}

__device__ __forceinline__ void cp16(uint32_t saddr, const void* gptr) {
    asm volatile("cp.async.cg.shared.global [%0], [%1], 16;" :: "r"(saddr), "l"(gptr));
}
__device__ __forceinline__ void cp_commit() {
    asm volatile("cp.async.commit_group;");
}
__device__ __forceinline__ void cp_wait1() {
    asm volatile("cp.async.wait_group 1;");
}
__device__ __forceinline__ void cp_wait0() {
    asm volatile("cp.async.wait_group 0;");
}

// ---------------------------------------------------------------------------
// NT core: C[128,128 tile] = alpha * A @ B^T. BK=16, 3-stage cp.async.
// dsm layout per stage (floats): As 128x20, Bs 128x20 -> 5120; 3 stages.
// Post-LDS tf32 conversion (identical numerics to pre-store cvt).
// Epilogue staged through smem for coalesced float4 stores.
// ---------------------------------------------------------------------------
__device__ __forceinline__ void gemm_nt_core(
    const float* __restrict__ A, const float* __restrict__ B, float* __restrict__ C,
    int K, int lda, int ldb, int ldc, float alpha,
    int mBase, int nBase, float* dsm)
{
    const int tid  = threadIdx.x;
    const int lane = tid & 31;
    const int warp = tid >> 5;
    const int wm   = warp >> 2;
    const int wn   = warp & 3;
    const int q    = lane & 3;
    const int lr   = lane >> 2;
    const int r0   = tid >> 2;
    const int c4   = (tid & 3) << 2;

    const uint32_t sbase = (uint32_t)__cvta_generic_to_shared(dsm);
    const float* Ag = A + (size_t)mBase * lda;
    const float* Bg = B + (size_t)nBase * ldb;

    float acc[4][4][4];
    #pragma unroll
    for (int i = 0; i < 4; i++)
        #pragma unroll
        for (int j = 0; j < 4; j++)
            #pragma unroll
            for (int t = 0; t < 4; t++) acc[i][j][t] = 0.f;

    const int nc = K >> 4;

    // issue stage st covering k0
    #define NT_ISSUE(st, k0) do {                                              \
        uint32_t ab = sbase + (st) * 20480u + (uint32_t)(r0 * 80 + c4 * 4);    \
        uint32_t bb = ab + 10240u;                                             \
        cp16(ab,          Ag + (size_t)r0 * lda + (k0) + c4);                  \
        cp16(ab + 5120u,  Ag + (size_t)(r0 + 64) * lda + (k0) + c4);           \
        cp16(bb,          Bg + (size_t)r0 * ldb + (k0) + c4);                  \
        cp16(bb + 5120u,  Bg + (size_t)(r0 + 64) * ldb + (k0) + c4);           \
        cp_commit();                                                           \
    } while (0)

    NT_ISSUE(0, 0);
    if (nc > 1) NT_ISSUE(1, 16);

    for (int ch = 0; ch < nc; ch++) {
        if (ch + 1 < nc) cp_wait1(); else cp_wait0();
        __syncthreads();

        const float* As_ = dsm + (ch % 3) * 5120;
        const float* Bs_ = As_ + 2560;

        #pragma unroll
        for (int ks = 0; ks < 2; ks++) {
            const int kb = ks * 8 + q;
            uint32_t af[4][4], bf[4][2];
            #pragma unroll
            for (int mi = 0; mi < 4; mi++) {
                const int m0 = wm * 64 + mi * 16 + lr;
                af[mi][0] = f2tf32(As_[m0 * 20 + kb]);
                af[mi][1] = f2tf32(As_[(m0 + 8) * 20 + kb]);
                af[mi][2] = f2tf32(As_[m0 * 20 + kb + 4]);
                af[mi][3] = f2tf32(As_[(m0 + 8) * 20 + kb + 4]);
            }
            #pragma unroll
            for (int ni = 0; ni < 4; ni++) {
                const int n0 = wn * 32 + ni * 8 + lr;
                bf[ni][0] = f2tf32(Bs_[n0 * 20 + kb]);
                bf[ni][1] = f2tf32(Bs_[n0 * 20 + kb + 4]);
            }
            #pragma unroll
            for (int mi = 0; mi < 4; mi++)
                #pragma unroll
                for (int ni = 0; ni < 4; ni++)
                    mma_tf32(acc[mi][ni], af[mi], bf[ni]);
        }
        __syncthreads();
        if (ch + 2 < nc) NT_ISSUE((ch + 2) % 3, (ch + 2) * 16);
    }
    #undef NT_ISSUE

    // ---- staged epilogue: two 64x128 halves through smem ----
    float* stg = dsm;                       // 64 x 132 view
    #pragma unroll
    for (int half = 0; half < 2; half++) {
        if (wm == half) {
            #pragma unroll
            for (int mi = 0; mi < 4; mi++) {
                const int rr = mi * 16 + lr;
                #pragma unroll
                for (int ni = 0; ni < 4; ni++) {
                    const int cc = wn * 32 + ni * 8 + q * 2;
                    stg[rr * 132 + cc]           = acc[mi][ni][0] * alpha;
                    stg[rr * 132 + cc + 1]       = acc[mi][ni][1] * alpha;
                    stg[(rr + 8) * 132 + cc]     = acc[mi][ni][2] * alpha;
                    stg[(rr + 8) * 132 + cc + 1] = acc[mi][ni][3] * alpha;
                }
            }
        }
        __syncthreads();
        #pragma unroll
        for (int i = 0; i < 8; i++) {
            const int row = (tid >> 5) * 8 + i;
            const int col = (tid & 31) * 4;
            *(float4*)&C[(size_t)(mBase + half * 64 + row) * ldc + nBase + col] =
                *(const float4*)&stg[row * 132 + col];
        }
        __syncthreads();
    }
}

// ---------------------------------------------------------------------------
__global__ __launch_bounds__(256, 2) void qkv_proj_kernel(
    const float* __restrict__ q, const float* __restrict__ k, const float* __restrict__ v,
    const float* __restrict__ Wq, const float* __restrict__ Wk, const float* __restrict__ Wv,
    float* __restrict__ qp, float* __restrict__ kp, float* __restrict__ vp)
{
    extern __shared__ float dsm[];
    const float* A; const float* B; float* C;
    if (blockIdx.z == 0)      { A = q; B = Wq; C = qp; }
    else if (blockIdx.z == 1) { A = k; B = Wk; C = kp; }
    else                      { A = v; B = Wv; C = vp; }
    gemm_nt_core(A, B, C, DMODEL, DMODEL, DMODEL, DMODEL, 1.f,
                 blockIdx.y * 128, blockIdx.x * 128, dsm);
}

__global__ __launch_bounds__(256, 2) void out_proj_kernel(
    const float* __restrict__ A, const float* __restrict__ B, float* __restrict__ C)
{
    extern __shared__ float dsm[];
    gemm_nt_core(A, B, C, DMODEL, DMODEL, DMODEL, DMODEL, 1.f,
                 blockIdx.y * 128, blockIdx.x * 128, dsm);
}

__global__ __launch_bounds__(256, 2) void scores_kernel(
    const float* __restrict__ qp, const float* __restrict__ kp, float* __restrict__ wts)
{
    extern __shared__ float dsm[];
    const int bh = blockIdx.z;
    const int b = bh >> 4, h = bh & 15;
    const float* A = qp + (size_t)b * SEQ * DMODEL + h * DK;
    const float* B = kp + (size_t)b * SEQ * DMODEL + h * DK;
    float*       C = wts + (size_t)bh * SEQ * SEQ;
    gemm_nt_core(A, B, C, DK, DMODEL, DMODEL, SEQ, 0.125f,
                 blockIdx.y * 128, blockIdx.x * 128, dsm);
}

// ---------------------------------------------------------------------------
// Row softmax, in place: 65536 rows of length 2048.
// ---------------------------------------------------------------------------
__global__ __launch_bounds__(256) void softmax_kernel(float* __restrict__ Wt)
{
    float* row = Wt + (size_t)blockIdx.x * SEQ;
    const int tid = threadIdx.x;
    __shared__ float red[8];

    float v[8];
    float m = -1e30f;
    #pragma unroll
    for (int i = 0; i < 8; i++) {
        v[i] = row[tid + 256 * i];
        m = fmaxf(m, v[i]);
    }
    #pragma unroll
    for (int o = 16; o; o >>= 1) m = fmaxf(m, __shfl_xor_sync(0xFFFFFFFFu, m, o));
    if ((tid & 31) == 0) red[tid >> 5] = m;
    __syncthreads();
    m = red[0];
    #pragma unroll
    for (int i = 1; i < 8; i++) m = fmaxf(m, red[i]);
    __syncthreads();

    float e[8];
    float s = 0.f;
    #pragma unroll
    for (int i = 0; i < 8; i++) { e[i] = __expf(v[i] - m); s += e[i]; }
    #pragma unroll
    for (int o = 16; o; o >>= 1) s += __shfl_xor_sync(0xFFFFFFFFu, s, o);
    if ((tid & 31) == 0) red[tid >> 5] = s;
    __syncthreads();
    s = red[0];
    #pragma unroll
    for (int i = 1; i < 8; i++) s += red[i];
    const float inv = 1.f / s;

    #pragma unroll
    for (int i = 0; i < 8; i++) row[tid + 256 * i] = e[i] * inv;
}

// ---------------------------------------------------------------------------
// PV: C[M,64] = A[M,K] @ B[K,64], 3-stage cp.async, staged epilogue.
// smem per stage: As 128x20 (2560) + Bs 16x72 (1152) = 3712 floats.
// ---------------------------------------------------------------------------
__global__ __launch_bounds__(256, 2) void pv_async_kernel(
    const float* __restrict__ P, const float* __restrict__ V, float* __restrict__ C)
{
    __shared__ float sm[3 * 3712];

    const int z = blockIdx.z;
    const int b = z >> 4, h = z & 15;
    const int mBase = blockIdx.y * 128;

    const float* Ag = P + (size_t)z * SEQ * SEQ + (size_t)mBase * SEQ;
    const float* Bg = V + (size_t)b * SEQ * DMODEL + h * DK;
    float*       Cg = C + (size_t)b * SEQ * DMODEL + h * DK + (size_t)mBase * DMODEL;

    const int tid  = threadIdx.x;
    const int lane = tid & 31;
    const int warp = tid >> 5;
    const int wm   = warp >> 1;        // 0..3 -> m offset wm*32
    const int wn   = warp & 1;         // 0..1 -> n offset wn*32
    const int q    = lane & 3;
    const int lr   = lane >> 2;
    const int r0   = tid >> 2;
    const int c4   = (tid & 3) << 2;
    const int kr   = tid >> 4;         // 0..15
    const int n4   = (tid & 15) << 2;  // 0..60

    const uint32_t sbase = (uint32_t)__cvta_generic_to_shared(sm);

    float acc[2][4][4];
    #pragma unroll
    for (int i = 0; i < 2; i++)
        #pragma unroll
        for (int j = 0; j < 4; j++)
            #pragma unroll
            for (int t = 0; t < 4; t++) acc[i][j][t] = 0.f;

    #define PV_ISSUE(st, k0) do {                                               \
        uint32_t ab = sbase + (st) * 14848u + (uint32_t)(r0 * 80 + c4 * 4);     \
        uint32_t bb = sbase + (st) * 14848u + 10240u + (uint32_t)(kr * 288 + n4 * 4); \
        cp16(ab,         Ag + (size_t)r0 * SEQ + (k0) + c4);                    \
        cp16(ab + 5120u, Ag + (size_t)(r0 + 64) * SEQ + (k0) + c4);             \
        cp16(bb,         Bg + (size_t)((k0) + kr) * DMODEL + n4);               \
        cp_commit();                                                            \
    } while (0)

    const int nc = SEQ >> 4;           // 128
    PV_ISSUE(0, 0);
    PV_ISSUE(1, 16);

    for (int ch = 0; ch < nc; ch++) {
        if (ch + 1 < nc) cp_wait1(); else cp_wait0();
        __syncthreads();

        const float* As_ = sm + (ch % 3) * 3712;
        const float* Bs_ = As_ + 2560;

        #pragma unroll
        for (int ks = 0; ks < 2; ks++) {
            const int kb = ks * 8 + q;
            uint32_t af[2][4], bf[4][2];
            #pragma unroll
            for (int mi = 0; mi < 2; mi++) {
                const int m0 = wm * 32 + mi * 16 + lr;
                af[mi][0] = f2tf32(As_[m0 * 20 + kb]);
                af[mi][1] = f2tf32(As_[(m0 + 8) * 20 + kb]);
                af[mi][2] = f2tf32(As_[m0 * 20 + kb + 4]);
                af[mi][3] = f2tf32(As_[(m0 + 8) * 20 + kb + 4]);
            }
            #pragma unroll
            for (int ni = 0; ni < 4; ni++) {
                const int n0 = wn * 32 + ni * 8 + lr;
                bf[ni][0] = f2tf32(Bs_[kb * 72 + n0]);
                bf[ni][1] = f2tf32(Bs_[(kb + 4) * 72 + n0]);
            }
            #pragma unroll
            for (int mi = 0; mi < 2; mi++)
                #pragma unroll
                for (int ni = 0; ni < 4; ni++)
                    mma_tf32(acc[mi][ni], af[mi], bf[ni]);
        }
        __syncthreads();
        if (ch + 2 < nc) PV_ISSUE((ch + 2) % 3, (ch + 2) * 16);
    }
    #undef PV_ISSUE

    // ---- staged epilogue: full 128x64 tile through smem (128x68 view) ----
    float* stg = sm;
    #pragma unroll
    for (int mi = 0; mi < 2; mi++) {
        const int rr = wm * 32 + mi * 16 + lr;
        #pragma unroll
        for (int ni = 0; ni < 4; ni++) {
            const int cc = wn * 32 + ni * 8 + q * 2;
            stg[rr * 68 + cc]           = acc[mi][ni][0];
            stg[rr * 68 + cc + 1]       = acc[mi][ni][1];
            stg[(rr + 8) * 68 + cc]     = acc[mi][ni][2];
            stg[(rr + 8) * 68 + cc + 1] = acc[mi][ni][3];
        }
    }
    __syncthreads();
    #pragma unroll
    for (int i = 0; i < 8; i++) {
        const int row = (tid >> 4) * 8 + i;
        const int col = (tid & 15) * 4;
        *(float4*)&Cg[(size_t)row * DMODEL + col] = *(const float4*)&stg[row * 68 + col];
    }
}

// ---------------------------------------------------------------------------
extern "C" void kernel_launch(void* const* d_in, const int* in_sizes, int n_in,
                              void* d_out, int out_size)
{
    const float* q  = (const float*)d_in[0];
    const float* k  = (const float*)d_in[1];
    const float* v  = (const float*)d_in[2];
    const float* Wq = (const float*)d_in[3];
    const float* Wk = (const float*)d_in[4];
    const float* Wv = (const float*)d_in[5];
    const float* Wo = (const float*)d_in[6];
    float* out = (float*)d_out;
    float* wts = out + OUT_OFF;

    float *qp, *kp, *vp, *ao;
    cudaGetSymbolAddress((void**)&qp, g_qp);
    cudaGetSymbolAddress((void**)&kp, g_kp);
    cudaGetSymbolAddress((void**)&vp, g_vp);
    cudaGetSymbolAddress((void**)&ao, g_ao);

    const int DSM = 3 * 20480;  // 61440 bytes
    cudaFuncSetAttribute(qkv_proj_kernel, cudaFuncAttributeMaxDynamicSharedMemorySize, DSM);
    cudaFuncSetAttribute(scores_kernel,  cudaFuncAttributeMaxDynamicSharedMemorySize, DSM);
    cudaFuncSetAttribute(out_proj_kernel, cudaFuncAttributeMaxDynamicSharedMemorySize, DSM);

    const dim3 thr(256);

    // Q/K/V projections in one launch
    qkv_proj_kernel<<<dim3(8, 32, 3), thr, DSM>>>(q, k, v, Wq, Wk, Wv, qp, kp, vp);

    // Scores: per (b,h) Qh @ Kh^T * 0.125
    scores_kernel<<<dim3(16, 16, 32), thr, DSM>>>(qp, kp, wts);

    // Softmax in place
    softmax_kernel<<<BATCH * NHEAD * SEQ, 256>>>(wts);

    // P @ V -> attn_out
    pv_async_kernel<<<dim3(1, 16, 32), thr>>>(wts, vp, ao);

    // Output projection
    out_proj_kernel<<<dim3(8, 32, 1), thr, DSM>>>(ao, Wo, out);
}